// round 14
// baseline (speedup 1.0000x reference)
#include <cuda_runtime.h>
#include <stdint.h>

#define NB 8
#define NC 80
#define NN 17328             /* 3*5776 */
#define NS 38                /* n-slices */
#define SLICE 456            /* NN / NS */
#define NBC (NB * NC)
#define TOPK 200
#define CAP 512
#define CAPS 64              /* per-(b,c,slice) segment capacity (pow2) */
#define NBINS 2048
#define PBINS 256
#define NW 7
#define HI_BITS 0x3F7AE000u  /* v >= 0.9799805f */
#define FULLM 0xFFFFFFFFu

// Static device scratch
__device__ unsigned long long g_items[(size_t)NB * NS * NC * CAPS];  // 12.5 MB
__device__ int g_cnt[NB * NS * NC];

// ---------------------------------------------------------------------------
// Kernel 1: collect_k — grid (NS, NB), 512 threads, prefetched float4 stream.
// ---------------------------------------------------------------------------
__global__ __launch_bounds__(512) void collect_k(const float* __restrict__ scores) {
    const int s = blockIdx.x;
    const int b = blockIdx.y;
    const int tid = threadIdx.x;

    __shared__ int cnt[NC];
    __shared__ unsigned long long items[NC * CAPS];   // 40 KB

    for (int i = tid; i < NC; i += 512) cnt[i] = 0;
    __syncthreads();

    const float4* src = reinterpret_cast<const float4*>(
        scores + ((size_t)b * NN + (size_t)s * SLICE) * NC);
    const int NF4 = SLICE * NC / 4;                   // 9120

    float4 v = src[tid];                              // tid < 512 < NF4 always
    for (int f = tid; f < NF4; f += 512) {
        const int fn = f + 512;
        float4 nxt;
        if (fn < NF4) nxt = src[fn];                  // prefetch next (MLP=2)
        uint32_t bb[4] = {__float_as_uint(v.x), __float_as_uint(v.y),
                          __float_as_uint(v.z), __float_as_uint(v.w)};
        int nloc = f / 20;
        int c0   = (f % 20) * 4;
        #pragma unroll
        for (int u = 0; u < 4; u++) {
            if (bb[u] >= HI_BITS) {
                int c = c0 + u;
                int p = atomicAdd(&cnt[c], 1);
                if (p < CAPS) {
                    uint32_t n = (uint32_t)(s * SLICE + nloc);
                    items[c * CAPS + p] =
                        ((unsigned long long)bb[u] << 32) | (~n);
                }
            }
        }
        v = nxt;
    }
    __syncthreads();

    for (int c = tid; c < NC; c += 512)
        g_cnt[(b * NS + s) * NC + c] = cnt[c];

    for (int idx = tid; idx < NC * CAPS; idx += 512) {
        int c = idx >> 6, k = idx & (CAPS - 1);
        int n = cnt[c]; if (n > CAPS) n = CAPS;
        if (k < n)
            g_items[((size_t)(b * NS + s) * NC + c) * CAPS + k] = items[idx];
    }
}

// ---------------------------------------------------------------------------
// Kernel 2: nms_k — one CTA (256 thr) per (b,c).
// ---------------------------------------------------------------------------
__device__ __forceinline__ uint32_t score_bin(uint32_t bits) {
    return (bits >= 0x3F800000u) ? (NBINS - 1) : ((bits - 0x3F000000u) >> 12);
}
__device__ __forceinline__ uint32_t precut_bin(uint32_t bits) {
    uint32_t d = (bits - HI_BITS) >> 11;
    return (d > (PBINS - 1)) ? (PBINS - 1) : d;
}
__device__ __forceinline__ unsigned long long bstep_shfl(
    unsigned long long v, int tid, int k, int j) {
    unsigned long long pv = __shfl_xor_sync(FULLM, v, j);
    bool keepMax = (((tid & j) == 0) == ((tid & k) == 0));
    return keepMax ? (v >= pv ? v : pv) : (v <= pv ? v : pv);
}

// Branch-free IoU>0.5 decision, exact-band semantics (matches reference fp32).
__device__ __forceinline__ bool iou_sup(const float4& bi, float ai,
                                        const float4& bj, float aj, bool valid) {
    float dx = fminf(bi.z, bj.z) - fmaxf(bi.x, bj.x);
    float dy = fminf(bi.w, bj.w) - fmaxf(bi.y, bj.y);
    float inter = fmaxf(dx, 0.f) * fmaxf(dy, 0.f);    // == ref max(0,.)*max(0,.)
    float s  = ai + aj;
    float t3 = 3.0f * inter;
    bool sup = (t3 > s * 1.00002f);
    if (!sup && t3 >= s * 0.99998f)                   // rare band: exact ref math
        sup = (inter / (s - inter) > 0.5f);
    return valid && sup;
}

struct NmsSmem {
    float4 sbox[TOPK];
    float  sar[TOPK];
    uint32_t smat[TOPK * NW];
    uint32_t skeepw[NW];
};

__global__ __launch_bounds__(256, 5) void nms_k(const float* __restrict__ boxes,
                                                const float* __restrict__ scores,
                                                float* __restrict__ out) {
    const int bc  = blockIdx.x;
    const int b   = bc / NC;
    const int c   = bc % NC;
    const int tid = threadIdx.x;
    const int lane = tid & 31;
    const int wid  = tid >> 5;

    __shared__ unsigned long long cand[CAP];          // 4 KB
    __shared__ unsigned long long cand2[256];         // 2 KB
    __shared__ union U {
        uint32_t hist[NBINS];                         // 8 KB (fallback)
        NmsSmem  m;                                   // ~9.6 KB
        __device__ U() {}
    } u;
    __shared__ int scnt[NS], soff[NS];
    __shared__ uint32_t part[256];
    __shared__ int totCnt, okFlag;
    __shared__ uint32_t candCnt, c2cnt;
    __shared__ int cutBin;

    if (tid < NS) scnt[tid] = g_cnt[(b * NS + tid) * NC + c];
    __syncthreads();
    if (tid == 0) {
        int run = 0, ok = 1;
        for (int s = 0; s < NS; s++) {
            soff[s] = run;
            int n = scnt[s];
            if (n > CAPS) ok = 0;
            run += n;
        }
        totCnt = run; okFlag = ok;
    }
    __syncthreads();

    const int tot = totCnt;
    const bool fast = okFlag && (tot >= TOPK) && (tot <= CAP);
    int cc;

    if (fast) {
        for (int idx = tid; idx < NS * CAPS; idx += 256) {
            int s = idx >> 6, k = idx & (CAPS - 1);
            if (k < scnt[s])
                cand[soff[s] + k] =
                    g_items[((size_t)(b * NS + s) * NC + c) * CAPS + k];
        }
        cc = tot;
        __syncthreads();
    } else {
        // ---- exactness fallback (cold) ----
        for (int i = tid; i < NBINS; i += 256) u.hist[i] = 0u;
        if (tid == 0) candCnt = 0u;
        __syncthreads();
        const float* base = scores + (size_t)b * NN * NC + c;
        for (int i = tid; i < NN; i += 256) {
            float v = base[(size_t)i * NC];
            if (v > 0.5f) atomicAdd(&u.hist[score_bin(__float_as_uint(v))], 1u);
        }
        __syncthreads();
        uint32_t ps = 0;
        #pragma unroll
        for (int k = 0; k < 8; k++) ps += u.hist[tid * 8 + k];
        part[tid] = ps;
        __syncthreads();
        if (tid == 0) {
            uint32_t suf = 0; int g = -1; uint32_t sufG = 0;
            for (int t = 255; t >= 0; t--) {
                uint32_t ns = suf + part[t];
                if (ns >= TOPK) { g = t; sufG = suf; break; }
                suf = ns;
            }
            int hstar = 0;
            if (g >= 0) {
                uint32_t run = sufG;
                for (int bn = g * 8 + 7; bn >= g * 8; bn--) {
                    run += u.hist[bn];
                    if (run >= TOPK) { hstar = bn; break; }
                }
            }
            cutBin = hstar;
        }
        __syncthreads();
        const int hstar = cutBin;
        for (int i = tid; i < NN; i += 256) {
            float v = base[(size_t)i * NC];
            if (v > 0.5f) {
                uint32_t bits = __float_as_uint(v);
                if (score_bin(bits) >= (uint32_t)hstar) {
                    uint32_t p = atomicAdd(&candCnt, 1u);
                    if (p < CAP)
                        cand[p] = ((unsigned long long)bits << 32) | (~(uint32_t)i);
                }
            }
        }
        __syncthreads();
        cc = (candCnt < (uint32_t)CAP) ? (int)candCnt : CAP;
    }

    // ---- pre-cut: 256-bin exact rank-200 cut, parallel suffix scan ----
    bool useC2 = false;
    int cc2 = 0;
    if (cc >= TOPK) {
        u.hist[tid] = 0u;
        if (tid == 0) { c2cnt = 0u; cutBin = 0; }
        __syncthreads();
        for (int i = tid; i < cc; i += 256)
            atomicAdd(&u.hist[precut_bin((uint32_t)(cand[i] >> 32))], 1u);
        __syncthreads();
        const int r = 255 - tid;
        uint32_t sx = u.hist[r];
        #pragma unroll
        for (int o = 1; o < 32; o <<= 1) {
            uint32_t t = __shfl_up_sync(FULLM, sx, o);
            if (lane >= o) sx += t;
        }
        if (lane == 31) part[wid] = sx;
        __syncthreads();
        if (tid == 0) {
            uint32_t run = 0;
            #pragma unroll
            for (int w = 0; w < 8; w++) { uint32_t t = part[w]; part[w] = run; run += t; }
        }
        __syncthreads();
        uint32_t suffix = sx + part[wid];
        if (suffix >= (uint32_t)TOPK) atomicMax(&cutBin, r);
        __syncthreads();
        const uint32_t h2 = (uint32_t)cutBin;
        for (int i = tid; i < cc; i += 256) {
            unsigned long long key = cand[i];
            if (precut_bin((uint32_t)(key >> 32)) >= h2) {
                uint32_t p = atomicAdd(&c2cnt, 1u);
                if (p < 256u) cand2[p] = key;
            }
        }
        __syncthreads();
        cc2 = (int)c2cnt;
        useC2 = (cc2 <= 256);
    }

    unsigned long long* sbuf = useC2 ? cand2 : cand;
    const int scc = useC2 ? cc2 : cc;
    const int M   = (scc <= 256) ? 256 : CAP;

    for (int i = tid; i < M; i += 256)
        if (i >= scc) sbuf[i] = 0ULL;
    __syncthreads();

    if (M == 256) {
        // hybrid register/shfl bitonic sort, descending
        unsigned long long v = sbuf[tid];
        #pragma unroll
        for (int k = 2; k <= 32; k <<= 1)
            for (int j = k >> 1; j > 0; j >>= 1)
                v = bstep_shfl(v, tid, k, j);
        #pragma unroll
        for (int k = 64; k <= 256; k <<= 1) {
            for (int j = k >> 1; j >= 32; j >>= 1) {
                __syncthreads();
                sbuf[tid] = v;
                __syncthreads();
                unsigned long long pv = sbuf[tid ^ j];
                bool keepMax = (((tid & j) == 0) == ((tid & k) == 0));
                v = keepMax ? (v >= pv ? v : pv) : (v <= pv ? v : pv);
            }
            #pragma unroll
            for (int j = 16; j > 0; j >>= 1)
                v = bstep_shfl(v, tid, k, j);
        }
        __syncthreads();
        sbuf[tid] = v;
        __syncthreads();
    } else {
        for (int k = 2; k <= M; k <<= 1) {
            for (int j = k >> 1; j > 0; j >>= 1) {
                for (int p = tid; p < (M >> 1); p += 256) {
                    int i   = ((p & ~(j - 1)) << 1) | (p & (j - 1));
                    int ixj = i | j;
                    unsigned long long a = sbuf[i], bb = sbuf[ixj];
                    bool desc = ((i & k) == 0);
                    if (desc ? (a < bb) : (a > bb)) { sbuf[i] = bb; sbuf[ixj] = a; }
                }
                __syncthreads();
            }
        }
    }

    const int nTop = (cc < TOPK) ? cc : TOPK;

    // ---- winners -> smem tables; zero smat ----
    if (tid < TOPK) {
        float4 bx = make_float4(0.f, 0.f, 0.f, 0.f);
        float ar = 0.f;
        if (tid < nTop) {
            unsigned long long key = sbuf[tid];
            uint32_t idx = ~(uint32_t)(key & 0xFFFFFFFFull);
            bx = reinterpret_cast<const float4*>(boxes)[(size_t)b * NN + idx];
            ar = (bx.z - bx.x) * (bx.w - bx.y);
        }
        u.m.sbox[tid] = bx;
        u.m.sar[tid]  = ar;
    }
    for (int i = tid; i < TOPK * NW; i += 256) u.m.smat[i] = 0u;
    __syncthreads();

    // ---- 64-wide ballot matrix: 4 column-units x 2 row-halves = 8 warps ----
    {
        const int uu   = wid >> 1;                 // column unit 0..3
        const int half = wid & 1;
        const int j0 = uu * 64 + lane;             // -> word 2*uu
        const int j1 = j0 + 32;                    // -> word 2*uu+1
        const bool v0 = (j0 < nTop), v1 = (j1 < nTop);
        float4 b0 = make_float4(0.f, 0.f, 0.f, 0.f), b1 = b0;
        float  a0 = 0.f, a1 = 0.f;
        if (v0) { b0 = u.m.sbox[j0]; a0 = u.m.sar[j0]; }
        if (v1) { b1 = u.m.sbox[j1]; a1 = u.m.sar[j1]; }
        const int iMax = (nTop < 64 * uu + 63) ? nTop : (64 * uu + 63);
        const int iBeg = half ? (iMax >> 1) : 0;
        const int iEnd = half ? iMax : (iMax >> 1);
        const int w0 = 2 * uu, w1 = 2 * uu + 1;
        #pragma unroll 2
        for (int i = iBeg; i < iEnd; i++) {
            float4 bi = u.m.sbox[i];
            float  ai = u.m.sar[i];
            bool s0 = iou_sup(bi, ai, b0, a0, v0 && (j0 > i));
            bool s1 = iou_sup(bi, ai, b1, a1, v1 && (j1 > i));
            uint32_t m0 = __ballot_sync(FULLM, s0);
            uint32_t m1 = __ballot_sync(FULLM, s1);
            if (lane == 0) {
                u.m.smat[i * NW + w0] = m0;
                if (w1 < NW) u.m.smat[i * NW + w1] = m1;
            }
        }
    }
    __syncthreads();

    // ---- branchless block-unrolled greedy scan ----
    if (tid == 0) {
        uint32_t rm[NW];
        #pragma unroll
        for (int w = 0; w < NW; w++) rm[w] = 0u;
        #pragma unroll
        for (int blk = 0; blk < NW; blk++) {
            const int nIb = (blk == NW - 1) ? (TOPK - blk * 32) : 32;
            #pragma unroll 4
            for (int ib = 0; ib < nIb; ib++) {
                const int i = blk * 32 + ib;
                uint32_t mask = ~(uint32_t)(((int)(rm[blk] << (31 - ib))) >> 31);
                #pragma unroll
                for (int w = blk; w < NW; w++)
                    rm[w] |= u.m.smat[i * NW + w] & mask;
            }
        }
        #pragma unroll
        for (int w = 0; w < NW; w++) u.m.skeepw[w] = ~rm[w];
    }
    __syncthreads();

    // ---- output (B, C, TOPK, 6) ----
    if (tid < TOPK) {
        bool kp = (tid < nTop) && ((u.m.skeepw[tid >> 5] >> (tid & 31)) & 1u);
        size_t o = ((size_t)bc * TOPK + tid) * 6;
        float4 bx = u.m.sbox[tid];
        float sc = (tid < nTop) ? __uint_as_float((uint32_t)(sbuf[tid] >> 32)) : 0.f;
        out[o + 0] = kp ? bx.x : 0.f;
        out[o + 1] = kp ? bx.y : 0.f;
        out[o + 2] = kp ? bx.z : 0.f;
        out[o + 3] = kp ? bx.w : 0.f;
        out[o + 4] = kp ? sc : 0.f;
        out[o + 5] = kp ? (float)c : 0.f;
    }
}

// ---------------------------------------------------------------------------
extern "C" void kernel_launch(void* const* d_in, const int* in_sizes, int n_in,
                              void* d_out, int out_size) {
    const float* boxes  = (const float*)d_in[0];   // (8, 3, 5776, 4)
    const float* scores = (const float*)d_in[1];   // (8, 3, 5776, 80)
    float* out = (float*)d_out;                    // (8, 80, 200, 6)

    dim3 gc(NS, NB);
    collect_k<<<gc, 512>>>(scores);
    nms_k<<<NBC, 256>>>(boxes, scores, out);
}

// round 15
// speedup vs baseline: 1.0755x; 1.0755x over previous
#include <cuda_runtime.h>
#include <stdint.h>

#define NB 8
#define NC 80
#define NN 17328             /* 3*5776 */
#define NS 38                /* n-slices */
#define SLICE 456            /* NN / NS */
#define NBC (NB * NC)
#define TOPK 200
#define CAP 512
#define CAPS 64              /* per-(b,c,slice) segment capacity (pow2) */
#define NBINS 2048
#define PBINS 256
#define NW 7
#define HI_BITS 0x3F7AE000u  /* v >= 0.9799805f */
#define FULLM 0xFFFFFFFFu

// Static device scratch
__device__ unsigned long long g_items[(size_t)NB * NS * NC * CAPS];  // 12.5 MB
__device__ int g_cnt[NB * NS * NC];

// ---------------------------------------------------------------------------
// Kernel 1: collect_k — grid (NS, NB), 512 threads.
// ---------------------------------------------------------------------------
__global__ __launch_bounds__(512) void collect_k(const float* __restrict__ scores) {
    const int s = blockIdx.x;
    const int b = blockIdx.y;
    const int tid = threadIdx.x;

    __shared__ int cnt[NC];
    __shared__ unsigned long long items[NC * CAPS];   // 40 KB

    for (int i = tid; i < NC; i += 512) cnt[i] = 0;
    __syncthreads();

    const float4* src = reinterpret_cast<const float4*>(
        scores + ((size_t)b * NN + (size_t)s * SLICE) * NC);
    const int NF4 = SLICE * NC / 4;                   // 9120

    for (int f = tid; f < NF4; f += 512) {
        float4 v = src[f];
        uint32_t bb[4] = {__float_as_uint(v.x), __float_as_uint(v.y),
                          __float_as_uint(v.z), __float_as_uint(v.w)};
        int nloc = f / 20;
        int c0   = (f % 20) * 4;
        #pragma unroll
        for (int u = 0; u < 4; u++) {
            if (bb[u] >= HI_BITS) {
                int c = c0 + u;
                int p = atomicAdd(&cnt[c], 1);
                if (p < CAPS) {
                    uint32_t n = (uint32_t)(s * SLICE + nloc);
                    items[c * CAPS + p] =
                        ((unsigned long long)bb[u] << 32) | (~n);
                }
            }
        }
    }
    __syncthreads();

    for (int c = tid; c < NC; c += 512)
        g_cnt[(b * NS + s) * NC + c] = cnt[c];

    for (int idx = tid; idx < NC * CAPS; idx += 512) {
        int c = idx >> 6, k = idx & (CAPS - 1);
        int n = cnt[c]; if (n > CAPS) n = CAPS;
        if (k < n)
            g_items[((size_t)(b * NS + s) * NC + c) * CAPS + k] = items[idx];
    }
}

// ---------------------------------------------------------------------------
// Kernel 2: nms_k — one CTA (256 thr) per (b,c).
// ---------------------------------------------------------------------------
__device__ __forceinline__ uint32_t score_bin(uint32_t bits) {
    return (bits >= 0x3F800000u) ? (NBINS - 1) : ((bits - 0x3F000000u) >> 12);
}
__device__ __forceinline__ uint32_t precut_bin(uint32_t bits) {
    uint32_t d = (bits - HI_BITS) >> 11;
    return (d > (PBINS - 1)) ? (PBINS - 1) : d;
}
__device__ __forceinline__ unsigned long long bstep_shfl(
    unsigned long long v, int tid, int k, int j) {
    unsigned long long pv = __shfl_xor_sync(FULLM, v, j);
    bool keepMax = (((tid & j) == 0) == ((tid & k) == 0));
    return keepMax ? (v >= pv ? v : pv) : (v <= pv ? v : pv);
}

struct NmsSmem {
    float4 sbox[TOPK];
    float  sar[TOPK];
    uint32_t smat[TOPK * NW];
    uint32_t skeepw[NW];
};

__global__ __launch_bounds__(256, 6) void nms_k(const float* __restrict__ boxes,
                                                const float* __restrict__ scores,
                                                float* __restrict__ out) {
    const int bc  = blockIdx.x;
    const int b   = bc / NC;
    const int c   = bc % NC;
    const int tid = threadIdx.x;
    const int lane = tid & 31;
    const int wid  = tid >> 5;

    __shared__ unsigned long long cand[CAP];          // 4 KB
    __shared__ unsigned long long cand2[256];         // 2 KB
    __shared__ union U {
        uint32_t hist[NBINS];                         // 8 KB (fallback)
        NmsSmem  m;                                   // ~9.6 KB
        __device__ U() {}
    } u;
    __shared__ int scnt[NS], soff[NS];
    __shared__ uint32_t part[256];
    __shared__ int totCnt, okFlag;
    __shared__ uint32_t candCnt, c2cnt;
    __shared__ int cutBin;

    if (tid < NS) scnt[tid] = g_cnt[(b * NS + tid) * NC + c];
    __syncthreads();
    if (tid == 0) {
        int run = 0, ok = 1;
        for (int s = 0; s < NS; s++) {
            soff[s] = run;
            int n = scnt[s];
            if (n > CAPS) ok = 0;
            run += n;
        }
        totCnt = run; okFlag = ok;
    }
    __syncthreads();

    const int tot = totCnt;
    const bool fast = okFlag && (tot >= TOPK) && (tot <= CAP);
    int cc;

    if (fast) {
        for (int idx = tid; idx < NS * CAPS; idx += 256) {
            int s = idx >> 6, k = idx & (CAPS - 1);
            if (k < scnt[s])
                cand[soff[s] + k] =
                    g_items[((size_t)(b * NS + s) * NC + c) * CAPS + k];
        }
        cc = tot;
        __syncthreads();
    } else {
        // ---- exactness fallback (cold) ----
        for (int i = tid; i < NBINS; i += 256) u.hist[i] = 0u;
        if (tid == 0) candCnt = 0u;
        __syncthreads();
        const float* base = scores + (size_t)b * NN * NC + c;
        for (int i = tid; i < NN; i += 256) {
            float v = base[(size_t)i * NC];
            if (v > 0.5f) atomicAdd(&u.hist[score_bin(__float_as_uint(v))], 1u);
        }
        __syncthreads();
        uint32_t ps = 0;
        #pragma unroll
        for (int k = 0; k < 8; k++) ps += u.hist[tid * 8 + k];
        part[tid] = ps;
        __syncthreads();
        if (tid == 0) {
            uint32_t suf = 0; int g = -1; uint32_t sufG = 0;
            for (int t = 255; t >= 0; t--) {
                uint32_t ns = suf + part[t];
                if (ns >= TOPK) { g = t; sufG = suf; break; }
                suf = ns;
            }
            int hstar = 0;
            if (g >= 0) {
                uint32_t run = sufG;
                for (int bn = g * 8 + 7; bn >= g * 8; bn--) {
                    run += u.hist[bn];
                    if (run >= TOPK) { hstar = bn; break; }
                }
            }
            cutBin = hstar;
        }
        __syncthreads();
        const int hstar = cutBin;
        for (int i = tid; i < NN; i += 256) {
            float v = base[(size_t)i * NC];
            if (v > 0.5f) {
                uint32_t bits = __float_as_uint(v);
                if (score_bin(bits) >= (uint32_t)hstar) {
                    uint32_t p = atomicAdd(&candCnt, 1u);
                    if (p < CAP)
                        cand[p] = ((unsigned long long)bits << 32) | (~(uint32_t)i);
                }
            }
        }
        __syncthreads();
        cc = (candCnt < (uint32_t)CAP) ? (int)candCnt : CAP;
    }

    // ---- pre-cut: 256-bin exact rank-200 cut, parallel suffix scan ----
    bool useC2 = false;
    int cc2 = 0;
    if (cc >= TOPK) {
        u.hist[tid] = 0u;
        if (tid == 0) { c2cnt = 0u; cutBin = 0; }
        __syncthreads();
        for (int i = tid; i < cc; i += 256)
            atomicAdd(&u.hist[precut_bin((uint32_t)(cand[i] >> 32))], 1u);
        __syncthreads();
        const int r = 255 - tid;
        uint32_t sx = u.hist[r];
        #pragma unroll
        for (int o = 1; o < 32; o <<= 1) {
            uint32_t t = __shfl_up_sync(FULLM, sx, o);
            if (lane >= o) sx += t;
        }
        if (lane == 31) part[wid] = sx;
        __syncthreads();
        if (tid == 0) {
            uint32_t run = 0;
            #pragma unroll
            for (int w = 0; w < 8; w++) { uint32_t t = part[w]; part[w] = run; run += t; }
        }
        __syncthreads();
        uint32_t suffix = sx + part[wid];
        if (suffix >= (uint32_t)TOPK) atomicMax(&cutBin, r);
        __syncthreads();
        const uint32_t h2 = (uint32_t)cutBin;
        for (int i = tid; i < cc; i += 256) {
            unsigned long long key = cand[i];
            if (precut_bin((uint32_t)(key >> 32)) >= h2) {
                uint32_t p = atomicAdd(&c2cnt, 1u);
                if (p < 256u) cand2[p] = key;
            }
        }
        __syncthreads();
        cc2 = (int)c2cnt;
        useC2 = (cc2 <= 256);
    }

    unsigned long long* sbuf = useC2 ? cand2 : cand;
    const int scc = useC2 ? cc2 : cc;
    const int M   = (scc <= 256) ? 256 : CAP;

    for (int i = tid; i < M; i += 256)
        if (i >= scc) sbuf[i] = 0ULL;
    __syncthreads();

    if (M == 256) {
        // hybrid register/shfl bitonic sort, descending
        unsigned long long v = sbuf[tid];
        #pragma unroll
        for (int k = 2; k <= 32; k <<= 1)
            for (int j = k >> 1; j > 0; j >>= 1)
                v = bstep_shfl(v, tid, k, j);
        #pragma unroll
        for (int k = 64; k <= 256; k <<= 1) {
            for (int j = k >> 1; j >= 32; j >>= 1) {
                __syncthreads();
                sbuf[tid] = v;
                __syncthreads();
                unsigned long long pv = sbuf[tid ^ j];
                bool keepMax = (((tid & j) == 0) == ((tid & k) == 0));
                v = keepMax ? (v >= pv ? v : pv) : (v <= pv ? v : pv);
            }
            #pragma unroll
            for (int j = 16; j > 0; j >>= 1)
                v = bstep_shfl(v, tid, k, j);
        }
        __syncthreads();
        sbuf[tid] = v;
        __syncthreads();
    } else {
        for (int k = 2; k <= M; k <<= 1) {
            for (int j = k >> 1; j > 0; j >>= 1) {
                for (int p = tid; p < (M >> 1); p += 256) {
                    int i   = ((p & ~(j - 1)) << 1) | (p & (j - 1));
                    int ixj = i | j;
                    unsigned long long a = sbuf[i], bb = sbuf[ixj];
                    bool desc = ((i & k) == 0);
                    if (desc ? (a < bb) : (a > bb)) { sbuf[i] = bb; sbuf[ixj] = a; }
                }
                __syncthreads();
            }
        }
    }

    const int nTop = (cc < TOPK) ? cc : TOPK;

    // ---- winners -> smem tables; zero smat ----
    if (tid < TOPK) {
        float4 bx = make_float4(0.f, 0.f, 0.f, 0.f);
        float ar = 0.f;
        if (tid < nTop) {
            unsigned long long key = sbuf[tid];
            uint32_t idx = ~(uint32_t)(key & 0xFFFFFFFFull);
            bx = reinterpret_cast<const float4*>(boxes)[(size_t)b * NN + idx];
            ar = (bx.z - bx.x) * (bx.w - bx.y);
        }
        u.m.sbox[tid] = bx;
        u.m.sar[tid]  = ar;
    }
    for (int i = tid; i < TOPK * NW; i += 256) u.m.smat[i] = 0u;
    __syncthreads();

    // ---- balanced triangular ballot matrix: 14 half-units / 8 warps.
    //      Per-lane predicates (valid, j>i) folded into a per-row word mask. ----
    {
        int units[2];
        units[0] = wid;
        units[1] = (wid < 6) ? (13 - wid) : -1;
        #pragma unroll
        for (int t = 0; t < 2; t++) {
            int uu = units[t];
            if (uu < 0) continue;
            const int w    = uu >> 1;
            const int half = uu & 1;
            const int j    = w * 32 + lane;
            float4 bj = make_float4(0.f, 0.f, 0.f, 0.f);
            float  aj = 0.f;
            if (j < nTop) { bj = u.m.sbox[j]; aj = u.m.sar[j]; }
            // word validity mask: bits for j < nTop in this word
            const int vn = nTop - 32 * w;
            const uint32_t validMask =
                (vn >= 32) ? 0xFFFFFFFFu : ((vn <= 0) ? 0u : ((1u << vn) - 1u));
            const int iMax = (nTop < 32 * w + 31) ? nTop : (32 * w + 31);
            const int iBeg = half ? (iMax >> 1) : 0;
            const int iEnd = half ? iMax : (iMax >> 1);
            const int w32  = 32 * w;
            #pragma unroll 2
            for (int i = iBeg; i < iEnd; i++) {
                float4 bi = u.m.sbox[i];
                float  ai = u.m.sar[i];
                // bare IoU decision (garbage lanes masked out below)
                float dx = fminf(bi.z, bj.z) - fmaxf(bi.x, bj.x);
                float dy = fminf(bi.w, bj.w) - fmaxf(bi.y, bj.y);
                float inter = fmaxf(dx, 0.f) * fmaxf(dy, 0.f);
                float s  = ai + aj;
                float t3 = 3.0f * inter;
                bool sup = (t3 > s * 1.00002f);
                if (!sup && t3 >= s * 0.99998f)       // rare band: exact ref math
                    sup = (inter / (s - inter) > 0.5f);
                uint32_t m = __ballot_sync(FULLM, sup);
                if (lane == 0) {
                    uint32_t jm = validMask;
                    if (i >= w32) jm &= (0xFFFFFFFEu << (i - w32));  // j > i
                    u.m.smat[i * NW + w] = m & jm;
                }
            }
        }
    }
    __syncthreads();

    // ---- branchless block-unrolled greedy scan ----
    if (tid == 0) {
        uint32_t rm[NW];
        #pragma unroll
        for (int w = 0; w < NW; w++) rm[w] = 0u;
        #pragma unroll
        for (int blk = 0; blk < NW; blk++) {
            const int nIb = (blk == NW - 1) ? (TOPK - blk * 32) : 32;
            #pragma unroll 4
            for (int ib = 0; ib < nIb; ib++) {
                const int i = blk * 32 + ib;
                uint32_t mask = ~(uint32_t)(((int)(rm[blk] << (31 - ib))) >> 31);
                #pragma unroll
                for (int w = blk; w < NW; w++)
                    rm[w] |= u.m.smat[i * NW + w] & mask;
            }
        }
        #pragma unroll
        for (int w = 0; w < NW; w++) u.m.skeepw[w] = ~rm[w];
    }
    __syncthreads();

    // ---- output (B, C, TOPK, 6) ----
    if (tid < TOPK) {
        bool kp = (tid < nTop) && ((u.m.skeepw[tid >> 5] >> (tid & 31)) & 1u);
        size_t o = ((size_t)bc * TOPK + tid) * 6;
        float4 bx = u.m.sbox[tid];
        float sc = (tid < nTop) ? __uint_as_float((uint32_t)(sbuf[tid] >> 32)) : 0.f;
        out[o + 0] = kp ? bx.x : 0.f;
        out[o + 1] = kp ? bx.y : 0.f;
        out[o + 2] = kp ? bx.z : 0.f;
        out[o + 3] = kp ? bx.w : 0.f;
        out[o + 4] = kp ? sc : 0.f;
        out[o + 5] = kp ? (float)c : 0.f;
    }
}

// ---------------------------------------------------------------------------
extern "C" void kernel_launch(void* const* d_in, const int* in_sizes, int n_in,
                              void* d_out, int out_size) {
    const float* boxes  = (const float*)d_in[0];   // (8, 3, 5776, 4)
    const float* scores = (const float*)d_in[1];   // (8, 3, 5776, 80)
    float* out = (float*)d_out;                    // (8, 80, 200, 6)

    dim3 gc(NS, NB);
    collect_k<<<gc, 512>>>(scores);
    nms_k<<<NBC, 256>>>(boxes, scores, out);
}

// round 16
// speedup vs baseline: 1.1523x; 1.0714x over previous
#include <cuda_runtime.h>
#include <stdint.h>

#define NB 8
#define NC 80
#define NN 17328             /* 3*5776 */
#define NS 76                /* n-slices */
#define SLICE 228            /* NN / NS */
#define NBC (NB * NC)
#define TOPK 200
#define CAP 512
#define CAPS 32              /* per-(b,c,slice) segment capacity (pow2) */
#define NBINS 2048
#define PBINS 256
#define NW 7
#define HI_BITS 0x3F7AE000u  /* v >= 0.9799805f */
#define FULLM 0xFFFFFFFFu

// Static device scratch
__device__ unsigned long long g_items[(size_t)NB * NS * NC * CAPS];  // 12.5 MB
__device__ int g_cnt[NB * NS * NC];

// ---------------------------------------------------------------------------
// Kernel 1: collect_k — grid (NS, NB), 512 threads, 20 KB smem.
// ---------------------------------------------------------------------------
__global__ __launch_bounds__(512) void collect_k(const float* __restrict__ scores) {
    const int s = blockIdx.x;
    const int b = blockIdx.y;
    const int tid = threadIdx.x;

    __shared__ int cnt[NC];
    __shared__ unsigned long long items[NC * CAPS];   // 20 KB

    for (int i = tid; i < NC; i += 512) cnt[i] = 0;
    __syncthreads();

    const float4* src = reinterpret_cast<const float4*>(
        scores + ((size_t)b * NN + (size_t)s * SLICE) * NC);
    const int NF4 = SLICE * NC / 4;                   // 4560

    for (int f = tid; f < NF4; f += 512) {
        float4 v = src[f];
        uint32_t bb[4] = {__float_as_uint(v.x), __float_as_uint(v.y),
                          __float_as_uint(v.z), __float_as_uint(v.w)};
        int nloc = f / 20;
        int c0   = (f % 20) * 4;
        #pragma unroll
        for (int u = 0; u < 4; u++) {
            if (bb[u] >= HI_BITS) {
                int c = c0 + u;
                int p = atomicAdd(&cnt[c], 1);
                if (p < CAPS) {
                    uint32_t n = (uint32_t)(s * SLICE + nloc);
                    items[c * CAPS + p] =
                        ((unsigned long long)bb[u] << 32) | (~n);
                }
            }
        }
    }
    __syncthreads();

    for (int c = tid; c < NC; c += 512)
        g_cnt[(b * NS + s) * NC + c] = cnt[c];

    for (int idx = tid; idx < NC * CAPS; idx += 512) {
        int c = idx >> 5, k = idx & (CAPS - 1);
        int n = cnt[c]; if (n > CAPS) n = CAPS;
        if (k < n)
            g_items[((size_t)(b * NS + s) * NC + c) * CAPS + k] = items[idx];
    }
}

// ---------------------------------------------------------------------------
// Kernel 2: nms_k — one CTA (256 thr) per (b,c).
// ---------------------------------------------------------------------------
__device__ __forceinline__ uint32_t score_bin(uint32_t bits) {
    return (bits >= 0x3F800000u) ? (NBINS - 1) : ((bits - 0x3F000000u) >> 12);
}
__device__ __forceinline__ uint32_t precut_bin(uint32_t bits) {
    uint32_t d = (bits - HI_BITS) >> 11;
    return (d > (PBINS - 1)) ? (PBINS - 1) : d;
}
__device__ __forceinline__ unsigned long long bstep_shfl(
    unsigned long long v, int tid, int k, int j) {
    unsigned long long pv = __shfl_xor_sync(FULLM, v, j);
    bool keepMax = (((tid & j) == 0) == ((tid & k) == 0));
    return keepMax ? (v >= pv ? v : pv) : (v <= pv ? v : pv);
}

struct NmsSmem {
    float4 sbox[TOPK];
    float  sar[TOPK];
    uint32_t smat[TOPK * NW];
    uint32_t skeepw[NW];
};

// Balanced packing of the 14 triangular half-units (w = unit>>1, half = unit&1)
// onto 8 warps: loads {100,100,111,111,111,111,111,111} row-iterations.
__device__ __constant__ signed char UNIT_TBL[8][2] = {
    {13, -1}, {12, -1}, {11, 0}, {10, 1}, {9, 2}, {8, 3}, {7, 4}, {6, 5}
};

__global__ __launch_bounds__(256, 6) void nms_k(const float* __restrict__ boxes,
                                                const float* __restrict__ scores,
                                                float* __restrict__ out) {
    const int bc  = blockIdx.x;
    const int b   = bc / NC;
    const int c   = bc % NC;
    const int tid = threadIdx.x;
    const int lane = tid & 31;
    const int wid  = tid >> 5;

    __shared__ unsigned long long cand[CAP];          // 4 KB
    __shared__ unsigned long long cand2[256];         // 2 KB
    __shared__ union U {
        uint32_t hist[NBINS];                         // 8 KB (fallback)
        NmsSmem  m;                                   // ~9.6 KB
        __device__ U() {}
    } u;
    __shared__ int scnt[NS], soff[NS];
    __shared__ uint32_t part[256];
    __shared__ int totCnt, okFlag;
    __shared__ uint32_t candCnt, c2cnt;
    __shared__ int cutBin;

    if (tid < NS) scnt[tid] = g_cnt[(b * NS + tid) * NC + c];
    __syncthreads();
    if (tid == 0) {
        int run = 0, ok = 1;
        for (int s = 0; s < NS; s++) {
            soff[s] = run;
            int n = scnt[s];
            if (n > CAPS) ok = 0;
            run += n;
        }
        totCnt = run; okFlag = ok;
    }
    __syncthreads();

    const int tot = totCnt;
    const bool fast = okFlag && (tot >= TOPK) && (tot <= CAP);
    int cc;

    if (fast) {
        for (int idx = tid; idx < NS * CAPS; idx += 256) {
            int s = idx >> 5, k = idx & (CAPS - 1);
            if (k < scnt[s])
                cand[soff[s] + k] =
                    g_items[((size_t)(b * NS + s) * NC + c) * CAPS + k];
        }
        cc = tot;
        __syncthreads();
    } else {
        // ---- exactness fallback (cold) ----
        for (int i = tid; i < NBINS; i += 256) u.hist[i] = 0u;
        if (tid == 0) candCnt = 0u;
        __syncthreads();
        const float* base = scores + (size_t)b * NN * NC + c;
        for (int i = tid; i < NN; i += 256) {
            float v = base[(size_t)i * NC];
            if (v > 0.5f) atomicAdd(&u.hist[score_bin(__float_as_uint(v))], 1u);
        }
        __syncthreads();
        uint32_t ps = 0;
        #pragma unroll
        for (int k = 0; k < 8; k++) ps += u.hist[tid * 8 + k];
        part[tid] = ps;
        __syncthreads();
        if (tid == 0) {
            uint32_t suf = 0; int g = -1; uint32_t sufG = 0;
            for (int t = 255; t >= 0; t--) {
                uint32_t ns = suf + part[t];
                if (ns >= TOPK) { g = t; sufG = suf; break; }
                suf = ns;
            }
            int hstar = 0;
            if (g >= 0) {
                uint32_t run = sufG;
                for (int bn = g * 8 + 7; bn >= g * 8; bn--) {
                    run += u.hist[bn];
                    if (run >= TOPK) { hstar = bn; break; }
                }
            }
            cutBin = hstar;
        }
        __syncthreads();
        const int hstar = cutBin;
        for (int i = tid; i < NN; i += 256) {
            float v = base[(size_t)i * NC];
            if (v > 0.5f) {
                uint32_t bits = __float_as_uint(v);
                if (score_bin(bits) >= (uint32_t)hstar) {
                    uint32_t p = atomicAdd(&candCnt, 1u);
                    if (p < CAP)
                        cand[p] = ((unsigned long long)bits << 32) | (~(uint32_t)i);
                }
            }
        }
        __syncthreads();
        cc = (candCnt < (uint32_t)CAP) ? (int)candCnt : CAP;
    }

    // ---- pre-cut: 256-bin exact rank-200 cut, parallel suffix scan ----
    bool useC2 = false;
    int cc2 = 0;
    if (cc >= TOPK) {
        u.hist[tid] = 0u;
        if (tid == 0) { c2cnt = 0u; cutBin = 0; }
        __syncthreads();
        for (int i = tid; i < cc; i += 256)
            atomicAdd(&u.hist[precut_bin((uint32_t)(cand[i] >> 32))], 1u);
        __syncthreads();
        const int r = 255 - tid;
        uint32_t sx = u.hist[r];
        #pragma unroll
        for (int o = 1; o < 32; o <<= 1) {
            uint32_t t = __shfl_up_sync(FULLM, sx, o);
            if (lane >= o) sx += t;
        }
        if (lane == 31) part[wid] = sx;
        __syncthreads();
        if (tid == 0) {
            uint32_t run = 0;
            #pragma unroll
            for (int w = 0; w < 8; w++) { uint32_t t = part[w]; part[w] = run; run += t; }
        }
        __syncthreads();
        uint32_t suffix = sx + part[wid];
        if (suffix >= (uint32_t)TOPK) atomicMax(&cutBin, r);
        __syncthreads();
        const uint32_t h2 = (uint32_t)cutBin;
        for (int i = tid; i < cc; i += 256) {
            unsigned long long key = cand[i];
            if (precut_bin((uint32_t)(key >> 32)) >= h2) {
                uint32_t p = atomicAdd(&c2cnt, 1u);
                if (p < 256u) cand2[p] = key;
            }
        }
        __syncthreads();
        cc2 = (int)c2cnt;
        useC2 = (cc2 <= 256);
    }

    unsigned long long* sbuf = useC2 ? cand2 : cand;
    const int scc = useC2 ? cc2 : cc;
    const int M   = (scc <= 256) ? 256 : CAP;

    for (int i = tid; i < M; i += 256)
        if (i >= scc) sbuf[i] = 0ULL;
    __syncthreads();

    if (M == 256) {
        // hybrid register/shfl bitonic sort, descending
        unsigned long long v = sbuf[tid];
        #pragma unroll
        for (int k = 2; k <= 32; k <<= 1)
            for (int j = k >> 1; j > 0; j >>= 1)
                v = bstep_shfl(v, tid, k, j);
        #pragma unroll
        for (int k = 64; k <= 256; k <<= 1) {
            for (int j = k >> 1; j >= 32; j >>= 1) {
                __syncthreads();
                sbuf[tid] = v;
                __syncthreads();
                unsigned long long pv = sbuf[tid ^ j];
                bool keepMax = (((tid & j) == 0) == ((tid & k) == 0));
                v = keepMax ? (v >= pv ? v : pv) : (v <= pv ? v : pv);
            }
            #pragma unroll
            for (int j = 16; j > 0; j >>= 1)
                v = bstep_shfl(v, tid, k, j);
        }
        __syncthreads();
        sbuf[tid] = v;
        __syncthreads();
    } else {
        for (int k = 2; k <= M; k <<= 1) {
            for (int j = k >> 1; j > 0; j >>= 1) {
                for (int p = tid; p < (M >> 1); p += 256) {
                    int i   = ((p & ~(j - 1)) << 1) | (p & (j - 1));
                    int ixj = i | j;
                    unsigned long long a = sbuf[i], bb = sbuf[ixj];
                    bool desc = ((i & k) == 0);
                    if (desc ? (a < bb) : (a > bb)) { sbuf[i] = bb; sbuf[ixj] = a; }
                }
                __syncthreads();
            }
        }
    }

    const int nTop = (cc < TOPK) ? cc : TOPK;

    // ---- winners -> smem tables; zero smat ----
    if (tid < TOPK) {
        float4 bx = make_float4(0.f, 0.f, 0.f, 0.f);
        float ar = 0.f;
        if (tid < nTop) {
            unsigned long long key = sbuf[tid];
            uint32_t idx = ~(uint32_t)(key & 0xFFFFFFFFull);
            bx = reinterpret_cast<const float4*>(boxes)[(size_t)b * NN + idx];
            ar = (bx.z - bx.x) * (bx.w - bx.y);
        }
        u.m.sbox[tid] = bx;
        u.m.sar[tid]  = ar;
    }
    for (int i = tid; i < TOPK * NW; i += 256) u.m.smat[i] = 0u;
    __syncthreads();

    // ---- balanced triangular ballot matrix: 14 half-units packed onto
    //      8 warps with max load 111 row-iterations (R12 inner loop). ----
    {
        #pragma unroll
        for (int t = 0; t < 2; t++) {
            const int uu = UNIT_TBL[wid][t];
            if (uu < 0) continue;
            const int w    = uu >> 1;
            const int half = uu & 1;
            const int j    = w * 32 + lane;
            float4 bj = make_float4(0.f, 0.f, 0.f, 0.f);
            float  aj = 0.f;
            bool valid = (j < nTop);
            if (valid) { bj = u.m.sbox[j]; aj = u.m.sar[j]; }
            const int iMax = (nTop < 32 * w + 31) ? nTop : (32 * w + 31);
            const int iBeg = half ? (iMax >> 1) : 0;
            const int iEnd = half ? iMax : (iMax >> 1);
            #pragma unroll 2
            for (int i = iBeg; i < iEnd; i++) {
                float4 bi = u.m.sbox[i];
                float  ai = u.m.sar[i];
                bool sup = false;
                if (valid && j > i) {
                    float dx = fminf(bi.z, bj.z) - fmaxf(bi.x, bj.x);
                    float dy = fminf(bi.w, bj.w) - fmaxf(bi.y, bj.y);
                    if (dx > 0.f && dy > 0.f) {
                        float inter = dx * dy;
                        float s  = ai + aj;
                        float t3 = 3.0f * inter;
                        if (t3 > s * 1.00002f)       sup = true;
                        else if (t3 >= s * 0.99998f)
                            sup = (inter / (s - inter) > 0.5f);
                    }
                }
                uint32_t m = __ballot_sync(FULLM, sup);
                if (lane == 0) u.m.smat[i * NW + w] = m;
            }
        }
    }
    __syncthreads();

    // ---- branchless block-unrolled greedy scan ----
    if (tid == 0) {
        uint32_t rm[NW];
        #pragma unroll
        for (int w = 0; w < NW; w++) rm[w] = 0u;
        #pragma unroll
        for (int blk = 0; blk < NW; blk++) {
            const int nIb = (blk == NW - 1) ? (TOPK - blk * 32) : 32;
            #pragma unroll 4
            for (int ib = 0; ib < nIb; ib++) {
                const int i = blk * 32 + ib;
                uint32_t mask = ~(uint32_t)(((int)(rm[blk] << (31 - ib))) >> 31);
                #pragma unroll
                for (int w = blk; w < NW; w++)
                    rm[w] |= u.m.smat[i * NW + w] & mask;
            }
        }
        #pragma unroll
        for (int w = 0; w < NW; w++) u.m.skeepw[w] = ~rm[w];
    }
    __syncthreads();

    // ---- output (B, C, TOPK, 6) ----
    if (tid < TOPK) {
        bool kp = (tid < nTop) && ((u.m.skeepw[tid >> 5] >> (tid & 31)) & 1u);
        size_t o = ((size_t)bc * TOPK + tid) * 6;
        float4 bx = u.m.sbox[tid];
        float sc = (tid < nTop) ? __uint_as_float((uint32_t)(sbuf[tid] >> 32)) : 0.f;
        out[o + 0] = kp ? bx.x : 0.f;
        out[o + 1] = kp ? bx.y : 0.f;
        out[o + 2] = kp ? bx.z : 0.f;
        out[o + 3] = kp ? bx.w : 0.f;
        out[o + 4] = kp ? sc : 0.f;
        out[o + 5] = kp ? (float)c : 0.f;
    }
}

// ---------------------------------------------------------------------------
extern "C" void kernel_launch(void* const* d_in, const int* in_sizes, int n_in,
                              void* d_out, int out_size) {
    const float* boxes  = (const float*)d_in[0];   // (8, 3, 5776, 4)
    const float* scores = (const float*)d_in[1];   // (8, 3, 5776, 80)
    float* out = (float*)d_out;                    // (8, 80, 200, 6)

    dim3 gc(NS, NB);
    collect_k<<<gc, 512>>>(scores);
    nms_k<<<NBC, 256>>>(boxes, scores, out);
}